// round 3
// baseline (speedup 1.0000x reference)
#include <cuda_runtime.h>

#define BATCH 32
#define SEQ   512
#define HID   256
#define TMEL  2000
#define T_TILE 64
#define H4    (HID / 4)   // 64 float4 per row

__global__ __launch_bounds__(256)
void length_regulator_kernel(const float* __restrict__ x,
                             const int* __restrict__ duration,
                             float* __restrict__ out,
                             int out_size) {
    const int b   = blockIdx.y;
    const int t0  = blockIdx.x * T_TILE;
    const int tid = threadIdx.x;
    const int wid  = tid >> 5;
    const int lane5 = tid & 31;

    __shared__ int csum[SEQ];
    __shared__ int wsum[8];
    __shared__ int idxs[T_TILE];

    // ---- Scan: each thread owns a pair of durations (2*tid, 2*tid+1). ----
    const int2* dur2 = (const int2*)(duration + b * SEQ);
    int2 d = dur2[tid];               // d.x = dur[2t], d.y = dur[2t+1]
    int s = d.x + d.y;                // pair sum

    // Warp-inclusive scan of pair sums (5 shuffles, no barriers).
    int sc = s;
    #pragma unroll
    for (int off = 1; off < 32; off <<= 1) {
        int v = __shfl_up_sync(0xffffffffu, sc, off);
        if (lane5 >= off) sc += v;
    }
    if (lane5 == 31) wsum[wid] = sc;  // warp total
    __syncthreads();

    // Prefix of earlier warp totals (8 values, every thread reads them).
    int wprefix = 0;
    #pragma unroll
    for (int w = 0; w < 8; w++)
        wprefix += (w < wid) ? wsum[w] : 0;

    int inc_hi = sc + wprefix;        // inclusive cumsum at element 2t+1
    csum[2 * tid]     = inc_hi - d.y; // inclusive cumsum at element 2t
    csum[2 * tid + 1] = inc_hi;
    __syncthreads();

    // ---- searchsorted(cumsum, pos, side='right'), clipped to SEQ-1. ----
    if (tid < T_TILE) {
        int pos = t0 + tid;
        int lo = 0, hi = SEQ;
        while (lo < hi) {
            int mid = (lo + hi) >> 1;
            if (csum[mid] <= pos) lo = mid + 1; else hi = mid;
        }
        idxs[tid] = min(lo, SEQ - 1);
    }
    __syncthreads();

    // ---- Copy rows: 64 threads per row (64 float4 = 1KB contiguous write),
    //      4 rows per 256-thread pass. 32-bit indexing throughout. ----
    const float4* __restrict__ x4 = (const float4*)x + (b * SEQ) * H4;
    float4* __restrict__ out4 = (float4*)out + (b * TMEL + t0) * H4;
    const int lane = tid & 63;    // float4 index within the row
    const int rsub = tid >> 6;    // 0..3

    #pragma unroll 4
    for (int r = rsub; r < T_TILE; r += 4) {
        if (t0 + r < TMEL) {
            int src = idxs[r];
            out4[r * H4 + lane] = __ldg(&x4[src * H4 + lane]);
        }
    }

    // mel_len appended after the main output as float-cast values
    // (only written if the harness buffer actually includes it).
    if (blockIdx.x == 0 && tid == 255) {
        const int main_elems = BATCH * TMEL * HID;
        if (out_size >= main_elems + BATCH) {
            int total = inc_hi;   // thread 255 holds inclusive sum of all 512
            out[main_elems + b] = (float)min(total, TMEL);
        }
    }
}

extern "C" void kernel_launch(void* const* d_in, const int* in_sizes, int n_in,
                              void* d_out, int out_size) {
    const float* x        = (const float*)d_in[0];
    const int*   duration = (const int*)d_in[1];
    float*       out      = (float*)d_out;

    dim3 grid((TMEL + T_TILE - 1) / T_TILE, BATCH);  // (32, 32)
    length_regulator_kernel<<<grid, 256>>>(x, duration, out, out_size);
}